// round 16
// baseline (speedup 1.0000x reference)
#include <cuda_runtime.h>

// Problem constants (fixed by the reference)
#define E_EDGES   2000000
#define NSEG      100000
#define INV_TEMP  0.125f   // 1 / TEMPERATURE

// Scratch (no allocs allowed). Both arrays are zero-initialized at module
// load; the unique ending-warp of every non-empty segment resets its entries
// to zero after use, so every kernel_launch (and graph replay) sees zeros.
__device__ float    g_sum[NSEG];
__device__ unsigned g_cnt[NSEG];

// ---------------------------------------------------------------------------
// Index dtype detection: reference asks int64 but default JAX canonicalizes to
// int32. Probe 8 bytes at int64-position E/4: sorted uniform over [0,100000)
// -> int64 hi-word there is 0; int32 interpretation puts ~50000 there.
// ---------------------------------------------------------------------------
__device__ __forceinline__ bool index_is_64(const void* __restrict__ idx) {
    const int2 probe = __ldg(&((const int2*)idx)[E_EDGES / 4]);
    return probe.y == 0;
}

__device__ __forceinline__ int idx_at(const void* __restrict__ idx, bool is64, int e) {
    return is64 ? (int)__ldg(&((const long long*)idx)[e])
                : __ldg(&((const int*)idx)[e]);
}

// Release-ordered count add: orders ALL prior memory ops (exp STG + sum adds)
// before the count becomes visible. Pairs with the acquire poll below.
__device__ __forceinline__ void red_release_add(unsigned* p, unsigned v) {
    asm volatile("red.release.gpu.global.add.u32 [%0], %1;" :: "l"(p), "r"(v) : "memory");
}
__device__ __forceinline__ unsigned ld_acquire(const unsigned* p) {
    unsigned v;
    asm volatile("ld.acquire.gpu.global.u32 %0, [%1];" : "=r"(v) : "l"(p) : "memory");
    return v;
}

// ---------------------------------------------------------------------------
// Fused single-pass kernel.
// Phase A (identical core to the proven K1): 4 edges/warp, 8 lanes/edge,
// 4 front-batched LDG.128/thread; lane 0 stores raw exps + run-merged
// atomics to g_sum/g_cnt (count add = release).
// Phase B: the warp where a segment ENDS (unique, index sorted) walks back to
// find the segment start, acquire-polls g_cnt[s] == segment length (all
// contributions come from warps/blocks with <= IDs -> deadlock-free under
// monotonic block dispatch), then normalizes the segment through L2
// (__ldcg/__stcg) and zeroes g_sum/g_cnt for the next replay.
// ---------------------------------------------------------------------------
__global__ void __launch_bounds__(256, 8)
fused_segment_softmax_kernel(const float4* __restrict__ q,
                             const float4* __restrict__ k,
                             const void*   __restrict__ index,
                             float*        __restrict__ out) {
    const int tid  = blockIdx.x * blockDim.x + threadIdx.x;
    const int warp = tid >> 5;
    const int lane = tid & 31;
    const int g    = lane >> 3;       // edge within warp (0..3)
    const int sub  = lane & 7;        // lane within 8-group

    const long long base = ((long long)warp * 4 + g) * 16;

    // ---- Phase A: streaming dot + exp (unchanged from the roofline K1) ----
    const float4 qa = __ldcs(&q[base + sub]);
    const float4 qb = __ldcs(&q[base + sub + 8]);
    const float4 ka = __ldcs(&k[base + sub]);
    const float4 kb = __ldcs(&k[base + sub + 8]);

    float d = qa.x * ka.x + qa.y * ka.y + qa.z * ka.z + qa.w * ka.w
            + qb.x * kb.x + qb.y * kb.y + qb.z * kb.z + qb.w * kb.w;

    d += __shfl_xor_sync(0xFFFFFFFFu, d, 4);
    d += __shfl_xor_sync(0xFFFFFFFFu, d, 2);
    d += __shfl_xor_sync(0xFFFFFFFFu, d, 1);

    const float ex = __expf(d * INV_TEMP);
    const float e1 = __shfl_sync(0xFFFFFFFFu, ex, 8);
    const float e2 = __shfl_sync(0xFFFFFFFFu, ex, 16);
    const float e3 = __shfl_sync(0xFFFFFFFFu, ex, 24);

    const bool is64 = index_is_64(index);

    // Segment ids for this warp's 4 edges — warp-uniform broadcast loads.
    int s0, s1, s2, s3;
    if (is64) {
        const longlong2 sa = __ldg(reinterpret_cast<const longlong2*>(index) + warp * 2);
        const longlong2 sb = __ldg(reinterpret_cast<const longlong2*>(index) + warp * 2 + 1);
        s0 = (int)sa.x; s1 = (int)sa.y; s2 = (int)sb.x; s3 = (int)sb.y;
    } else {
        const int4 sv = __ldg(reinterpret_cast<const int4*>(index) + warp);
        s0 = sv.x; s1 = sv.y; s2 = sv.z; s3 = sv.w;
    }

    if (lane == 0) {
        // Raw numerators -> L2 (evict-normal; re-read in Phase B).
        __stcg(reinterpret_cast<float4*>(out) + warp, make_float4(ex, e1, e2, e3));

        // Run-merged sum + count atomics. Count add is RELEASE: it publishes
        // the exp store and the sum add for this run.
        float acc = ex; int cur = s0; unsigned cnt = 1;
        if (s1 == cur) { acc += e1; cnt++; }
        else { atomicAdd(&g_sum[cur], acc); red_release_add(&g_cnt[cur], cnt); cur = s1; acc = e1; cnt = 1; }
        if (s2 == cur) { acc += e2; cnt++; }
        else { atomicAdd(&g_sum[cur], acc); red_release_add(&g_cnt[cur], cnt); cur = s2; acc = e2; cnt = 1; }
        if (s3 == cur) { acc += e3; cnt++; }
        else { atomicAdd(&g_sum[cur], acc); red_release_add(&g_cnt[cur], cnt); cur = s3; acc = e3; cnt = 1; }
        atomicAdd(&g_sum[cur], acc); red_release_add(&g_cnt[cur], cnt);
    }

    // ---- Phase B: handle segments that END at one of this warp's edges ----
    const int e0 = warp * 4;
    int s4 = (e0 + 4 < E_EDGES) ? idx_at(index, is64, e0 + 4) : -1;
    const int sarr[5] = { s0, s1, s2, s3, s4 };

    #pragma unroll
    for (int j = 0; j < 4; j++) {
        const int s = sarr[j];
        if (s != sarr[j + 1]) {               // warp-uniform: segment s ends at edge e0+j
            const int end = e0 + j;

            // Warp-parallel backward search for the segment start.
            int lo = end;                      // lowest edge confirmed in s
            for (;;) {
                const int p = lo - 1 - lane;
                const int v = (p >= 0) ? idx_at(index, is64, p) : -1;
                const unsigned bal = __ballot_sync(0xFFFFFFFFu, v != s);
                if (bal) { lo -= (__ffs(bal) - 1); break; }
                lo -= 32;                      // all 32 probed are in s
            }
            const int start = lo;
            const unsigned len = (unsigned)(end - start + 1);

            // Acquire-poll until every contribution has been published, then
            // read the final sum, reset scratch for the next replay.
            float inv;
            if (lane == 0) {
                while (ld_acquire(&g_cnt[s]) != len) { __nanosleep(64); }
                const float S = __ldcg(&g_sum[s]);
                inv = __fdividef(1.0f, S);
                __stcg(&g_sum[s], 0.0f);
                __stcg(&g_cnt[s], 0u);
            }
            inv = __shfl_sync(0xFFFFFFFFu, inv, 0);
            __syncwarp();   // memory fence among lanes: lane 0's acquire covers all

            // Normalize the whole segment through L2 (coherent vs __stcg).
            for (int ee = start + lane; ee <= end; ee += 32) {
                const float v = __ldcg(&out[ee]);
                __stcg(&out[ee], v * inv);
            }
        }
    }
}

// ---------------------------------------------------------------------------
// Launch. Inputs in metadata order: q [E*64 f32], k [E*64 f32], index [E].
// Output: E f32. ONE kernel node.
// ---------------------------------------------------------------------------
extern "C" void kernel_launch(void* const* d_in, const int* in_sizes, int n_in,
                              void* d_out, int out_size) {
    const float4* q   = (const float4*)d_in[0];
    const float4* k   = (const float4*)d_in[1];
    const void*   idx = d_in[2];
    float*        out = (float*)d_out;

    // 4 edges per warp -> E*8 threads (divides 256 exactly: 62500 blocks)
    const long long total_threads = (long long)E_EDGES * 8;
    const int blocks = (int)(total_threads / 256);
    fused_segment_softmax_kernel<<<blocks, 256>>>(q, k, idx, out);
}

// round 17
// speedup vs baseline: 5.4888x; 5.4888x over previous
#include <cuda_runtime.h>

// Problem constants (fixed by the reference)
#define E_EDGES   2000000
#define NSEG      100000
#define INV_TEMP  0.125f   // 1 / TEMPERATURE

// Scratch (no allocs allowed): denominators + reciprocals.
// g_sum is zero-initialized at module load; rcp_kernel re-zeroes it every
// call, so each kernel_launch sees zeros -> deterministic across replays.
__device__ float g_sum[NSEG];
__device__ float g_rcp[NSEG];

// ---------------------------------------------------------------------------
// Index dtype detection: reference asks int64 but default JAX canonicalizes to
// int32. Probe 8 bytes at int64-position E/4: sorted uniform over [0,100000)
// -> int64 hi-word there is 0; int32 interpretation puts ~50000 there.
// ---------------------------------------------------------------------------
__device__ __forceinline__ bool index_is_64(const void* __restrict__ idx) {
    const int2 probe = __ldg(&((const int2*)idx)[E_EDGES / 4]);
    return probe.y == 0;
}

// ---------------------------------------------------------------------------
// K1 (at HBM roofline): 4 edges per warp, 8 lanes per edge, 4 front-batched
// LDG.128 per thread (MLP_p1=4, regs 26, occ ~90%, ~7.0 TB/s).
// q/k streamed (__ldcs); out stored __stcg and index read __ldg so both stay
// L2-resident (L2 = 126 MB) for K2's re-read.
// Traffic model: 1.040 GB DRAM @ 7.0 TB/s = 148.6 us = measured duration.
// NOTE (R16): single-pass fusion with acquire/release completion counts was
// tried and measured 5.5x WORSE (839 us, DRAM 16%) — GPU-scope sync on the
// hot path serializes the LTS stream. The 2-pass structure is load-bearing.
// ---------------------------------------------------------------------------
__global__ void __launch_bounds__(256)
score_exp_kernel(const float4* __restrict__ q,
                 const float4* __restrict__ k,
                 const void*   __restrict__ index,
                 float*        __restrict__ out) {
    const int tid  = blockIdx.x * blockDim.x + threadIdx.x;
    const int warp = tid >> 5;
    const int lane = tid & 31;
    const int g    = lane >> 3;       // edge within warp (0..3)
    const int sub  = lane & 7;        // lane within 8-group

    const long long e    = (long long)warp * 4 + g;
    const long long base = e * 16;    // float4 index of row start

    // Front-batched independent streaming loads (MLP_p1 = 4):
    const float4 qa = __ldcs(&q[base + sub]);
    const float4 qb = __ldcs(&q[base + sub + 8]);
    const float4 ka = __ldcs(&k[base + sub]);
    const float4 kb = __ldcs(&k[base + sub + 8]);

    float d0 = qa.x * ka.x + qa.y * ka.y + qa.z * ka.z + qa.w * ka.w;
    float d1 = qb.x * kb.x + qb.y * kb.y + qb.z * kb.z + qb.w * kb.w;
    float d  = d0 + d1;

    // Reduce within the 8-lane group (3 shuffles)
    d += __shfl_xor_sync(0xFFFFFFFFu, d, 4);
    d += __shfl_xor_sync(0xFFFFFFFFu, d, 2);
    d += __shfl_xor_sync(0xFFFFFFFFu, d, 1);

    // Every lane in group g now has edge g's score; exponentiate (MUFU).
    const float ex = __expf(d * INV_TEMP);

    // Gather the 4 group results to lane 0.
    const float e1 = __shfl_sync(0xFFFFFFFFu, ex, 8);
    const float e2 = __shfl_sync(0xFFFFFFFFu, ex, 16);
    const float e3 = __shfl_sync(0xFFFFFFFFu, ex, 24);

    if (lane == 0) {
        // One 16B store for 4 numerators; evict-normal -> stays in L2 for K2.
        __stcg(reinterpret_cast<float4*>(out) + warp, make_float4(ex, e1, e2, e3));

        // One vector load for 4 segment ids; cached -> L2-resident for K2.
        int s0, s1, s2, s3;
        if (index_is_64(index)) {
            const longlong2 sa = __ldg(reinterpret_cast<const longlong2*>(index) + warp * 2);
            const longlong2 sb = __ldg(reinterpret_cast<const longlong2*>(index) + warp * 2 + 1);
            s0 = (int)sa.x; s1 = (int)sa.y; s2 = (int)sb.x; s3 = (int)sb.y;
        } else {
            const int4 sv = __ldg(reinterpret_cast<const int4*>(index) + warp);
            s0 = sv.x; s1 = sv.y; s2 = sv.z; s3 = sv.w;
        }

        // Run-merge (index sorted -> usually one REDG per 4 edges).
        float acc = ex;
        int   cur = s0;
        if (s1 == cur) acc += e1; else { atomicAdd(&g_sum[cur], acc); cur = s1; acc = e1; }
        if (s2 == cur) acc += e2; else { atomicAdd(&g_sum[cur], acc); cur = s2; acc = e2; }
        if (s3 == cur) acc += e3; else { atomicAdd(&g_sum[cur], acc); cur = s3; acc = e3; }
        atomicAdd(&g_sum[cur], acc);
    }
}

// ---------------------------------------------------------------------------
// K1.5: reciprocal of denominators + self-reset of g_sum for the next replay.
// 8 segments/thread -> 12500 threads, 49 blocks, single wave.
// ---------------------------------------------------------------------------
__global__ void __launch_bounds__(256)
rcp_kernel() {
    const int i = blockIdx.x * blockDim.x + threadIdx.x;
    if (i >= NSEG / 8) return;
    float4 sa = reinterpret_cast<float4*>(g_sum)[i * 2];
    float4 sb = reinterpret_cast<float4*>(g_sum)[i * 2 + 1];
    float4 ra, rb;
    ra.x = __fdividef(1.0f, sa.x);
    ra.y = __fdividef(1.0f, sa.y);
    ra.z = __fdividef(1.0f, sa.z);
    ra.w = __fdividef(1.0f, sa.w);
    rb.x = __fdividef(1.0f, sb.x);
    rb.y = __fdividef(1.0f, sb.y);
    rb.z = __fdividef(1.0f, sb.z);
    rb.w = __fdividef(1.0f, sb.w);
    reinterpret_cast<float4*>(g_rcp)[i * 2]     = ra;
    reinterpret_cast<float4*>(g_rcp)[i * 2 + 1] = rb;
    const float4 z = make_float4(0.f, 0.f, 0.f, 0.f);
    reinterpret_cast<float4*>(g_sum)[i * 2]     = z;
    reinterpret_cast<float4*>(g_sum)[i * 2 + 1] = z;
}

// ---------------------------------------------------------------------------
// K2: normalize = multiply by reciprocal. 4 edges/thread, 1954 blocks.
// out/index are L2-resident from K1 -> loads are L2 hits; tail ~1.9 us total.
// ---------------------------------------------------------------------------
__global__ void __launch_bounds__(256)
normalize_kernel(const void* __restrict__ index,
                 float*      __restrict__ out) {
    const int t = blockIdx.x * blockDim.x + threadIdx.x;
    const int i = t * 4;
    if (i >= E_EDGES) return;

    const bool is64 = index_is_64(index);

    float4 o = __ldg(reinterpret_cast<const float4*>(out) + t);

    int s0, s1, s2, s3;
    if (!is64) {
        const int4 sv = __ldg(reinterpret_cast<const int4*>(index) + t);
        s0 = sv.x; s1 = sv.y; s2 = sv.z; s3 = sv.w;
    } else {
        const longlong2 sa = __ldg(reinterpret_cast<const longlong2*>(index) + t * 2);
        const longlong2 sb = __ldg(reinterpret_cast<const longlong2*>(index) + t * 2 + 1);
        s0 = (int)sa.x; s1 = (int)sa.y; s2 = (int)sb.x; s3 = (int)sb.y;
    }

    o.x *= __ldg(&g_rcp[s0]);
    o.y *= __ldg(&g_rcp[s1]);
    o.z *= __ldg(&g_rcp[s2]);
    o.w *= __ldg(&g_rcp[s3]);
    __stcs(reinterpret_cast<float4*>(out) + t, o);
}

// ---------------------------------------------------------------------------
// Launch. Inputs in metadata order: q [E*64 f32], k [E*64 f32], index [E].
// Output: E f32. Three kernel nodes: K1 -> rcp(+reset) -> K2.
// ---------------------------------------------------------------------------
extern "C" void kernel_launch(void* const* d_in, const int* in_sizes, int n_in,
                              void* d_out, int out_size) {
    const float4* q   = (const float4*)d_in[0];
    const float4* k   = (const float4*)d_in[1];
    const void*   idx = d_in[2];
    float*        out = (float*)d_out;

    // K1: 4 edges per warp -> E*8 threads (62500 blocks)
    {
        const long long total_threads = (long long)E_EDGES * 8;
        const int blocks = (int)(total_threads / 256);
        score_exp_kernel<<<blocks, 256>>>(q, k, idx, out);
    }

    // K1.5: reciprocals + reset (12500 threads, 49 blocks)
    rcp_kernel<<<(NSEG / 8 + 255) / 256, 256>>>();

    // K2: 4 edges per thread (500000 threads, 1954 blocks)
    {
        const int threads = E_EDGES / 4;
        normalize_kernel<<<(threads + 255) / 256, 256>>>(idx, out);
    }
}